// round 8
// baseline (speedup 1.0000x reference)
#include <cuda_runtime.h>

#define N_NODES 100000
#define F 64
#define N_EDGES 500000
#define NCH 9
#define NEG 0.2f
#define TILE 256
#define NT ((N_NODES + TILE - 1) / TILE)   // 391
#define M_GROUPS (NCH * N_NODES)           // 900000
#define M_EDGES  (NCH * N_EDGES)           // 4500000
#define NB_SCAN  ((M_GROUPS + 1023) / 1024) // 879

typedef unsigned long long ull;
typedef unsigned int uint;

// ---------------- scratch (device globals; no allocations allowed) ----------
__device__ float g_h1[(size_t)NCH * N_NODES * F];
__device__ float g_h2[(size_t)NCH * N_NODES * F];
__device__ float g_x1[(size_t)NCH * N_NODES * F];   // layer-1 normalized output
__device__ float g_x2[(size_t)NCH * N_NODES * F];   // layer-2 normalized output
__device__ float g_ss1[M_GROUPS];
__device__ float g_sd1[M_GROUPS];
__device__ float g_ws1[M_GROUPS];                   // self-loop weight
__device__ float g_ss2[M_GROUPS];
__device__ float g_sd2[M_GROUPS];
__device__ float g_ws2[M_GROUPS];
__device__ int   g_cnt[M_GROUPS];
__device__ int   g_off[M_GROUPS];
__device__ int   g_cur[M_GROUPS];
__device__ int   g_bsum[1024];
__device__ int   g_boff[1024];
__device__ ull   g_edge[M_EDGES];                   // packed (w<<32 | src)

// ---------------- f32x2 helpers ----------------
__device__ __forceinline__ ull fma2(ull a, ull b, ull c) {
    ull d;
    asm("fma.rn.f32x2 %0, %1, %2, %3;" : "=l"(d) : "l"(a), "l"(b), "l"(c));
    return d;
}
__device__ __forceinline__ ull dup2(float x) {
    ull r;
    asm("mov.b64 %0, {%1, %1};" : "=l"(r) : "f"(x));
    return r;
}
__device__ __forceinline__ void unpack2(ull v, float& lo, float& hi) {
    asm("mov.b64 {%0, %1}, %2;" : "=f"(lo), "=f"(hi) : "l"(v));
}

// ---------------- fused GEMM + scores + self-loop weight, all channels -----
__global__ __launch_bounds__(256, 2) void gat_gemm_all(
    const float* __restrict__ Xg,
    const float* __restrict__ Wall,
    const float* __restrict__ asall,
    const float* __restrict__ adall,
    const float* __restrict__ bprevall,
    int layer)
{
    extern __shared__ char smem[];
    float* Ws = (float*)smem;                              // [64][64] scalar, 16KB
    ull*   Xt = (ull*)(smem + 16384);                      // [64][130] row-pairs
    float* ash  = (float*)(smem + 16384 + 64 * 130 * 8);
    float* adsh = ash + F;
    float* bsh  = adsh + F;

    const int bx = blockIdx.x;
    const int c = bx / NT;
    const int tile = bx % NT;
    const int tid = threadIdx.x;
    const int rowbase = tile * TILE;

    const float* W = Wall + (size_t)c * F * F;
    for (int i = tid; i < F * F / 4; i += 256)
        ((float4*)Ws)[i] = ((const float4*)W)[i];
    if (tid < F) {
        ash[tid]  = asall[c * F + tid];
        adsh[tid] = adall[c * F + tid];
        bsh[tid]  = layer ? bprevall[c * F + tid] : 0.f;
    }
    __syncthreads();   // bsh read by Xt fill below (layer 1)

    const float* xin = g_x1 + (size_t)c * N_NODES * F;
    float* hout  = (layer ? g_h2 : g_h1) + (size_t)c * N_NODES * F;
    float* ssout = (layer ? g_ss2 : g_ss1) + (size_t)c * N_NODES;
    float* sdout = (layer ? g_sd2 : g_sd1) + (size_t)c * N_NODES;
    float* wsout = (layer ? g_ws2 : g_ws1) + (size_t)c * N_NODES;

    float* xtf = (float*)Xt;
    #pragma unroll
    for (int it = 0; it < 16; it++) {
        int lin = it * 256 + tid;
        int kg = lin >> 8;
        int row = lin & 255;
        int gr = rowbase + row;
        float4 v = make_float4(0.f, 0.f, 0.f, 0.f);
        if (gr < N_NODES) {
            if (layer == 0) {
                v = *(const float4*)&Xg[(size_t)gr * F + 4 * kg];
            } else {
                float4 a = *(const float4*)&xin[(size_t)gr * F + 4 * kg];
                v.x = fmaxf(a.x + bsh[4 * kg + 0], 0.f);
                v.y = fmaxf(a.y + bsh[4 * kg + 1], 0.f);
                v.z = fmaxf(a.z + bsh[4 * kg + 2], 0.f);
                v.w = fmaxf(a.w + bsh[4 * kg + 3], 0.f);
            }
        }
        int base = (4 * kg) * 260 + row;
        xtf[base]       = v.x;
        xtf[base + 260] = v.y;
        xtf[base + 520] = v.z;
        xtf[base + 780] = v.w;
    }
    __syncthreads();

    const int tx = tid & 7;
    const int ty = tid >> 3;
    const ull* xbase = Xt + 4 * ty;
    const float* wbase = Ws + 8 * tx;

    ull acc[4][8];
    #pragma unroll
    for (int i = 0; i < 4; i++)
        #pragma unroll
        for (int j = 0; j < 8; j++) acc[i][j] = 0ull;

    #pragma unroll 4
    for (int k = 0; k < F; k++) {
        float4 wa = *(const float4*)(wbase + k * 64);
        float4 wb = *(const float4*)(wbase + k * 64 + 4);
        ulonglong2 x01 = *(const ulonglong2*)(xbase + k * 130);
        ulonglong2 x23 = *(const ulonglong2*)(xbase + k * 130 + 2);
        ull wd[8];
        wd[0] = dup2(wa.x); wd[1] = dup2(wa.y); wd[2] = dup2(wa.z); wd[3] = dup2(wa.w);
        wd[4] = dup2(wb.x); wd[5] = dup2(wb.y); wd[6] = dup2(wb.z); wd[7] = dup2(wb.w);
        ull xs[4] = {x01.x, x01.y, x23.x, x23.y};
        #pragma unroll
        for (int i = 0; i < 4; i++)
            #pragma unroll
            for (int j = 0; j < 8; j++)
                acc[i][j] = fma2(xs[i], wd[j], acc[i][j]);
    }

    float av[8], dv[8];
    #pragma unroll
    for (int j = 0; j < 8; j++) { av[j] = ash[8 * tx + j]; dv[j] = adsh[8 * tx + j]; }

    float ps[8], pd[8];
    #pragma unroll
    for (int p = 0; p < 4; p++) {
        float lo[8], hi[8];
        #pragma unroll
        for (int j = 0; j < 8; j++) unpack2(acc[p][j], lo[j], hi[j]);
        float s0 = 0.f, d0 = 0.f, s1 = 0.f, d1 = 0.f;
        #pragma unroll
        for (int j = 0; j < 8; j++) {
            s0 += lo[j] * av[j]; d0 += lo[j] * dv[j];
            s1 += hi[j] * av[j]; d1 += hi[j] * dv[j];
        }
        ps[2 * p] = s0; pd[2 * p] = d0; ps[2 * p + 1] = s1; pd[2 * p + 1] = d1;
    }
    #pragma unroll
    for (int off = 1; off < 8; off <<= 1) {
        #pragma unroll
        for (int r = 0; r < 8; r++) {
            ps[r] += __shfl_xor_sync(0xffffffffu, ps[r], off);
            pd[r] += __shfl_xor_sync(0xffffffffu, pd[r], off);
        }
    }

    #pragma unroll
    for (int p = 0; p < 4; p++) {
        int r0 = rowbase + 8 * ty + 2 * p;
        int r1 = r0 + 1;
        float lo[8], hi[8];
        #pragma unroll
        for (int j = 0; j < 8; j++) unpack2(acc[p][j], lo[j], hi[j]);

        if (r0 < N_NODES) {
            *(float4*)&hout[(size_t)r0 * F + 8 * tx]     = make_float4(lo[0], lo[1], lo[2], lo[3]);
            *(float4*)&hout[(size_t)r0 * F + 8 * tx + 4] = make_float4(lo[4], lo[5], lo[6], lo[7]);
            if (tx == 0) {
                float e = ps[2 * p] + pd[2 * p]; e = e > 0.f ? e : NEG * e;
                ssout[r0] = ps[2 * p]; sdout[r0] = pd[2 * p]; wsout[r0] = __expf(e);
            }
        }
        if (r1 < N_NODES) {
            *(float4*)&hout[(size_t)r1 * F + 8 * tx]     = make_float4(hi[0], hi[1], hi[2], hi[3]);
            *(float4*)&hout[(size_t)r1 * F + 8 * tx + 4] = make_float4(hi[4], hi[5], hi[6], hi[7]);
            if (tx == 0) {
                float e = ps[2 * p + 1] + pd[2 * p + 1]; e = e > 0.f ? e : NEG * e;
                ssout[r1] = ps[2 * p + 1]; sdout[r1] = pd[2 * p + 1]; wsout[r1] = __expf(e);
            }
        }
    }
}

// ---------------- CSR build ----------------
__global__ __launch_bounds__(256) void k_zero()
{
    int i = blockIdx.x * 256 + threadIdx.x;
    if (i < M_GROUPS) g_cnt[i] = 0;
}

__global__ __launch_bounds__(256) void k_count(const int* __restrict__ EI, int layer)
{
    int t = blockIdx.x * 256 + threadIdx.x;
    if (t >= M_EDGES) return;
    int c = t / N_EDGES;
    int e = t - c * N_EDGES;
    int d = EI[((size_t)(c * 2 + layer) * 2 + 1) * N_EDGES + e];
    atomicAdd(&g_cnt[c * N_NODES + d], 1);
}

__global__ __launch_bounds__(256) void k_scan1()
{
    __shared__ int sh[256];
    int tid = threadIdx.x;
    int base = blockIdx.x * 1024 + tid * 4;
    int v0 = 0, v1 = 0, v2 = 0, v3 = 0;
    if (base + 3 < M_GROUPS) {
        int4 t = *(const int4*)&g_cnt[base];
        v0 = t.x; v1 = t.y; v2 = t.z; v3 = t.w;
    } else {
        if (base     < M_GROUPS) v0 = g_cnt[base];
        if (base + 1 < M_GROUPS) v1 = g_cnt[base + 1];
        if (base + 2 < M_GROUPS) v2 = g_cnt[base + 2];
        if (base + 3 < M_GROUPS) v3 = g_cnt[base + 3];
    }
    int tsum = v0 + v1 + v2 + v3;
    sh[tid] = tsum;
    __syncthreads();
    for (int off = 1; off < 256; off <<= 1) {
        int t = (tid >= off) ? sh[tid - off] : 0;
        __syncthreads();
        sh[tid] += t;
        __syncthreads();
    }
    int excl = sh[tid] - tsum;
    if (base     < M_GROUPS) g_off[base]     = excl;
    if (base + 1 < M_GROUPS) g_off[base + 1] = excl + v0;
    if (base + 2 < M_GROUPS) g_off[base + 2] = excl + v0 + v1;
    if (base + 3 < M_GROUPS) g_off[base + 3] = excl + v0 + v1 + v2;
    if (tid == 255) g_bsum[blockIdx.x] = sh[255];
}

__global__ __launch_bounds__(1024) void k_scan2()
{
    __shared__ int sh[1024];
    int tid = threadIdx.x;
    int v = (tid < NB_SCAN) ? g_bsum[tid] : 0;
    sh[tid] = v;
    __syncthreads();
    for (int off = 1; off < 1024; off <<= 1) {
        int t = (tid >= off) ? sh[tid - off] : 0;
        __syncthreads();
        sh[tid] += t;
        __syncthreads();
    }
    if (tid < NB_SCAN) g_boff[tid] = sh[tid] - v;
}

__global__ __launch_bounds__(256) void k_scan3()
{
    int i = blockIdx.x * 256 + threadIdx.x;
    if (i >= M_GROUPS) return;
    int v = g_off[i] + g_boff[i >> 10];
    g_off[i] = v;
    g_cur[i] = v;
}

// scatter + per-edge weight computation; packed (w, src) single 8B store
__global__ __launch_bounds__(256) void k_scatter(const int* __restrict__ EI, int layer)
{
    int t = blockIdx.x * 256 + threadIdx.x;
    if (t >= M_EDGES) return;
    int c = t / N_EDGES;
    int e = t - c * N_EDGES;
    const int* src = EI + ((size_t)(c * 2 + layer) * 2) * N_EDGES;
    const int* dst = src + N_EDGES;
    int s = src[e];
    int d = dst[e];
    const float* ss = (layer ? g_ss2 : g_ss1) + (size_t)c * N_NODES;
    const float* sd = (layer ? g_sd2 : g_sd1) + (size_t)c * N_NODES;
    float ev = __ldg(&ss[s]) + __ldg(&sd[d]);
    ev = ev > 0.f ? ev : NEG * ev;
    float w = __expf(ev);
    int pos = atomicAdd(&g_cur[c * N_NODES + d], 1);
    g_edge[pos] = ((ull)__float_as_uint(w) << 32) | (uint)s;
}

// ---------------- gather aggregation -> normalized x -----------------------
__global__ __launch_bounds__(256) void gat_aggregate(int layer)
{
    int gid = blockIdx.x * 256 + threadIdx.x;
    int g = gid >> 4;
    int j = gid & 15;
    if (g >= M_GROUPS) return;
    int c = g / N_NODES;
    int node = g - c * N_NODES;

    const float* h = (layer ? g_h2 : g_h1) + (size_t)c * N_NODES * F;
    float wself = (layer ? g_ws2 : g_ws1)[g];
    float* xout = (layer ? g_x2 : g_x1) + (size_t)c * N_NODES * F;

    float4 hv = *(const float4*)&h[(size_t)node * F + 4 * j];
    float4 accA = make_float4(wself * hv.x, wself * hv.y, wself * hv.z, wself * hv.w);
    float4 accB = make_float4(0.f, 0.f, 0.f, 0.f);
    float denA = wself, denB = 0.f;

    int start = g_off[g];
    int end = (g == M_GROUPS - 1) ? M_EDGES : g_off[g + 1];
    int i = start;
    for (; i + 2 <= end; i += 2) {
        ull p0 = __ldg(&g_edge[i]);
        ull p1 = __ldg(&g_edge[i + 1]);
        int s0 = (int)(uint)p0;
        int s1 = (int)(uint)p1;
        float w0 = __uint_as_float((uint)(p0 >> 32));
        float w1 = __uint_as_float((uint)(p1 >> 32));
        float4 v0 = *(const float4*)&h[(size_t)s0 * F + 4 * j];
        float4 v1 = *(const float4*)&h[(size_t)s1 * F + 4 * j];
        accA.x += w0 * v0.x; accA.y += w0 * v0.y; accA.z += w0 * v0.z; accA.w += w0 * v0.w;
        denA += w0;
        accB.x += w1 * v1.x; accB.y += w1 * v1.y; accB.z += w1 * v1.z; accB.w += w1 * v1.w;
        denB += w1;
    }
    if (i < end) {
        ull p0 = __ldg(&g_edge[i]);
        int s0 = (int)(uint)p0;
        float w0 = __uint_as_float((uint)(p0 >> 32));
        float4 v0 = *(const float4*)&h[(size_t)s0 * F + 4 * j];
        accA.x += w0 * v0.x; accA.y += w0 * v0.y; accA.z += w0 * v0.z; accA.w += w0 * v0.w;
        denA += w0;
    }
    float den = denA + denB;
    float inv = 1.f / den;
    *(float4*)&xout[(size_t)node * F + 4 * j] =
        make_float4((accA.x + accB.x) * inv, (accA.y + accB.y) * inv,
                    (accA.z + accB.z) * inv, (accA.w + accB.w) * inv);
}

// ---------------- channel attention combine (x2 already normalized) --------
__global__ __launch_bounds__(256) void gat_final(
    const float* __restrict__ b2, const float* __restrict__ att, float* __restrict__ out)
{
    __shared__ float attsh[NCH * F];
    __shared__ float b2sh[NCH * F];
    for (int i = threadIdx.x; i < NCH * F; i += 256) { attsh[i] = att[i]; b2sh[i] = b2[i]; }
    __syncthreads();

    int tid = blockIdx.x * 256 + threadIdx.x;
    int node = tid >> 4;
    int j = tid & 15;
    if (node >= N_NODES) return;

    float4 xs[NCH];
    float sc[NCH];
    #pragma unroll
    for (int c = 0; c < NCH; c++) {
        float4 v = *(const float4*)&g_x2[((size_t)c * N_NODES + node) * F + 4 * j];
        int cb = c * F + 4 * j;
        v.x += b2sh[cb + 0];
        v.y += b2sh[cb + 1];
        v.z += b2sh[cb + 2];
        v.w += b2sh[cb + 3];
        xs[c] = v;
        sc[c] = v.x * attsh[cb + 0] + v.y * attsh[cb + 1] + v.z * attsh[cb + 2] + v.w * attsh[cb + 3];
    }
    #pragma unroll
    for (int off = 1; off < 16; off <<= 1) {
        #pragma unroll
        for (int c = 0; c < NCH; c++) sc[c] += __shfl_xor_sync(0xffffffffu, sc[c], off);
    }
    float mx = sc[0];
    #pragma unroll
    for (int c = 1; c < NCH; c++) mx = fmaxf(mx, sc[c]);
    float sum = 0.f;
    float wch[NCH];
    #pragma unroll
    for (int c = 0; c < NCH; c++) { wch[c] = __expf(sc[c] - mx); sum += wch[c]; }
    float inv = 1.f / sum;
    float4 o = make_float4(0.f, 0.f, 0.f, 0.f);
    #pragma unroll
    for (int c = 0; c < NCH; c++) {
        float a = wch[c] * inv;
        o.x += a * xs[c].x; o.y += a * xs[c].y; o.z += a * xs[c].z; o.w += a * xs[c].w;
    }
    *(float4*)&out[(size_t)node * F + 4 * j] = o;
}

// ---------------- launch ----------------
extern "C" void kernel_launch(void* const* d_in, const int* in_sizes, int n_in,
                              void* d_out, int out_size)
{
    const float* emb = (const float*)d_in[0];
    const float* W1  = (const float*)d_in[1];
    const float* as1 = (const float*)d_in[2];
    const float* ad1 = (const float*)d_in[3];
    const float* b1  = (const float*)d_in[4];
    const float* W2  = (const float*)d_in[5];
    const float* as2 = (const float*)d_in[6];
    const float* ad2 = (const float*)d_in[7];
    const float* b2  = (const float*)d_in[8];
    const float* att = (const float*)d_in[9];
    const int*   EI  = (const int*)d_in[10];
    float* out = (float*)d_out;

    const int smem_bytes = 16384 + 64 * 130 * 8 + 3 * F * 4;  // 83712
    cudaFuncSetAttribute(gat_gemm_all, cudaFuncAttributeMaxDynamicSharedMemorySize, smem_bytes);

    const int gemm_grid  = NCH * NT;                       // 3519
    const int grp_grid   = (M_GROUPS + 255) / 256;
    const int edge_grid  = (M_EDGES + 255) / 256;
    const int agg_grid   = (M_GROUPS * 16 + 255) / 256;
    const int fin_grid   = (N_NODES * 16 + 255) / 256;

    for (int layer = 0; layer < 2; layer++) {
        // CSR count/scan depends only on EI — run before gemm so the
        // profiler's capture window (4th launch) lands on gat_gemm_all.
        k_zero<<<grp_grid, 256>>>();
        k_count<<<edge_grid, 256>>>(EI, layer);
        k_scan1<<<NB_SCAN, 256>>>();
        gat_gemm_all<<<gemm_grid, 256, smem_bytes>>>(
            emb, layer ? W2 : W1, layer ? as2 : as1, layer ? ad2 : ad1, b1, layer);
        k_scan2<<<1, 1024>>>();
        k_scan3<<<grp_grid, 256>>>();
        k_scatter<<<edge_grid, 256>>>(EI, layer);
        gat_aggregate<<<agg_grid, 256>>>(layer);
    }
    gat_final<<<fin_grid, 256>>>(b2, att, out);
}

// round 9
// speedup vs baseline: 1.1510x; 1.1510x over previous
#include <cuda_runtime.h>

#define N_NODES 100000
#define F 64
#define N_EDGES 500000
#define NCH 9
#define NEG 0.2f
#define TILE 256
#define NT ((N_NODES + TILE - 1) / TILE)   // 391
#define M_GROUPS (NCH * N_NODES)           // 900000
#define M_EDGES  (NCH * N_EDGES)           // 4500000
#define NB_SCAN  ((M_GROUPS + 1023) / 1024) // 879

typedef unsigned long long ull;
typedef unsigned int uint;

// ---------------- scratch (device globals; no allocations allowed) ----------
__device__ float g_h1[(size_t)NCH * N_NODES * F];
__device__ float g_h2[(size_t)NCH * N_NODES * F];
__device__ float g_x1[(size_t)NCH * N_NODES * F];   // layer-1 normalized output
__device__ float g_x2[(size_t)NCH * N_NODES * F];   // layer-2 normalized output
__device__ float g_ss1[M_GROUPS];
__device__ float g_sd1[M_GROUPS];
__device__ float g_ws1[M_GROUPS];                   // self-loop weight
__device__ float g_ss2[M_GROUPS];
__device__ float g_sd2[M_GROUPS];
__device__ float g_ws2[M_GROUPS];
__device__ int   g_cnt[M_GROUPS];
__device__ int   g_off[M_GROUPS];
__device__ int   g_cur[M_GROUPS];
__device__ int   g_bsum[1024];
__device__ int   g_boff[1024];
__device__ ull   g_edge[M_EDGES];                   // packed (w<<32 | src)

// ---------------- f32x2 helpers ----------------
__device__ __forceinline__ ull fma2(ull a, ull b, ull c) {
    ull d;
    asm("fma.rn.f32x2 %0, %1, %2, %3;" : "=l"(d) : "l"(a), "l"(b), "l"(c));
    return d;
}
__device__ __forceinline__ ull dup2(float x) {
    ull r;
    asm("mov.b64 %0, {%1, %1};" : "=l"(r) : "f"(x));
    return r;
}
__device__ __forceinline__ void unpack2(ull v, float& lo, float& hi) {
    asm("mov.b64 {%0, %1}, %2;" : "=f"(lo), "=f"(hi) : "l"(v));
}

// ---------------- layer-0 GEMM: one X tile, all 9 channels in-block --------
__global__ __launch_bounds__(256, 2) void gat_gemm_l0(
    const float* __restrict__ Xg,
    const float* __restrict__ Wall,
    const float* __restrict__ asall,
    const float* __restrict__ adall)
{
    extern __shared__ char smem[];
    float* Ws = (float*)smem;                              // [64][64] scalar, 16KB
    ull*   Xt = (ull*)(smem + 16384);                      // [64][130] row-pairs

    const int tile = blockIdx.x;
    const int tid = threadIdx.x;
    const int rowbase = tile * TILE;

    // ---- fill Xt from embeddings once ----
    float* xtf = (float*)Xt;
    #pragma unroll
    for (int it = 0; it < 16; it++) {
        int lin = it * 256 + tid;
        int kg = lin >> 8;
        int row = lin & 255;
        int gr = rowbase + row;
        float4 v = make_float4(0.f, 0.f, 0.f, 0.f);
        if (gr < N_NODES) v = *(const float4*)&Xg[(size_t)gr * F + 4 * kg];
        int base = (4 * kg) * 260 + row;
        xtf[base]       = v.x;
        xtf[base + 260] = v.y;
        xtf[base + 520] = v.z;
        xtf[base + 780] = v.w;
    }

    const int tx = tid & 7;
    const int ty = tid >> 3;
    const ull* xbase = Xt + 4 * ty;
    const float* wbase = Ws + 8 * tx;

    for (int c = 0; c < NCH; c++) {
        __syncthreads();   // iter 0: Xt fill done; iter>0: prior Ws reads done
        const float* W = Wall + (size_t)c * F * F;
        for (int i = tid; i < F * F / 4; i += 256)
            ((float4*)Ws)[i] = ((const float4*)W)[i];
        __syncthreads();

        ull acc[4][8];
        #pragma unroll
        for (int i = 0; i < 4; i++)
            #pragma unroll
            for (int j = 0; j < 8; j++) acc[i][j] = 0ull;

        #pragma unroll 4
        for (int k = 0; k < F; k++) {
            float4 wa = *(const float4*)(wbase + k * 64);
            float4 wb = *(const float4*)(wbase + k * 64 + 4);
            ulonglong2 x01 = *(const ulonglong2*)(xbase + k * 130);
            ulonglong2 x23 = *(const ulonglong2*)(xbase + k * 130 + 2);
            ull wd[8];
            wd[0] = dup2(wa.x); wd[1] = dup2(wa.y); wd[2] = dup2(wa.z); wd[3] = dup2(wa.w);
            wd[4] = dup2(wb.x); wd[5] = dup2(wb.y); wd[6] = dup2(wb.z); wd[7] = dup2(wb.w);
            ull xs[4] = {x01.x, x01.y, x23.x, x23.y};
            #pragma unroll
            for (int i = 0; i < 4; i++)
                #pragma unroll
                for (int j = 0; j < 8; j++)
                    acc[i][j] = fma2(xs[i], wd[j], acc[i][j]);
        }

        float* hout  = g_h1 + (size_t)c * N_NODES * F;
        float* ssout = g_ss1 + (size_t)c * N_NODES;
        float* sdout = g_sd1 + (size_t)c * N_NODES;
        float* wsout = g_ws1 + (size_t)c * N_NODES;

        float av[8], dv[8];
        #pragma unroll
        for (int j = 0; j < 8; j++) {
            av[j] = __ldg(&asall[c * F + 8 * tx + j]);
            dv[j] = __ldg(&adall[c * F + 8 * tx + j]);
        }

        float ps[8], pd[8];
        #pragma unroll
        for (int p = 0; p < 4; p++) {
            float lo[8], hi[8];
            #pragma unroll
            for (int j = 0; j < 8; j++) unpack2(acc[p][j], lo[j], hi[j]);
            float s0 = 0.f, d0 = 0.f, s1 = 0.f, d1 = 0.f;
            #pragma unroll
            for (int j = 0; j < 8; j++) {
                s0 += lo[j] * av[j]; d0 += lo[j] * dv[j];
                s1 += hi[j] * av[j]; d1 += hi[j] * dv[j];
            }
            ps[2 * p] = s0; pd[2 * p] = d0; ps[2 * p + 1] = s1; pd[2 * p + 1] = d1;
        }
        #pragma unroll
        for (int off = 1; off < 8; off <<= 1) {
            #pragma unroll
            for (int r = 0; r < 8; r++) {
                ps[r] += __shfl_xor_sync(0xffffffffu, ps[r], off);
                pd[r] += __shfl_xor_sync(0xffffffffu, pd[r], off);
            }
        }

        #pragma unroll
        for (int p = 0; p < 4; p++) {
            int r0 = rowbase + 8 * ty + 2 * p;
            int r1 = r0 + 1;
            float lo[8], hi[8];
            #pragma unroll
            for (int j = 0; j < 8; j++) unpack2(acc[p][j], lo[j], hi[j]);

            if (r0 < N_NODES) {
                *(float4*)&hout[(size_t)r0 * F + 8 * tx]     = make_float4(lo[0], lo[1], lo[2], lo[3]);
                *(float4*)&hout[(size_t)r0 * F + 8 * tx + 4] = make_float4(lo[4], lo[5], lo[6], lo[7]);
                if (tx == 0) {
                    float e = ps[2 * p] + pd[2 * p]; e = e > 0.f ? e : NEG * e;
                    ssout[r0] = ps[2 * p]; sdout[r0] = pd[2 * p]; wsout[r0] = __expf(e);
                }
            }
            if (r1 < N_NODES) {
                *(float4*)&hout[(size_t)r1 * F + 8 * tx]     = make_float4(hi[0], hi[1], hi[2], hi[3]);
                *(float4*)&hout[(size_t)r1 * F + 8 * tx + 4] = make_float4(hi[4], hi[5], hi[6], hi[7]);
                if (tx == 0) {
                    float e = ps[2 * p + 1] + pd[2 * p + 1]; e = e > 0.f ? e : NEG * e;
                    ssout[r1] = ps[2 * p + 1]; sdout[r1] = pd[2 * p + 1]; wsout[r1] = __expf(e);
                }
            }
        }
    }
}

// ---------------- layer-1 GEMM: per (channel, tile) block ------------------
__global__ __launch_bounds__(256, 2) void gat_gemm_l1(
    const float* __restrict__ Wall,
    const float* __restrict__ asall,
    const float* __restrict__ adall,
    const float* __restrict__ b1all)
{
    extern __shared__ char smem[];
    float* Ws = (float*)smem;                              // 16KB
    ull*   Xt = (ull*)(smem + 16384);                      // [64][130]
    float* ash  = (float*)(smem + 16384 + 64 * 130 * 8);
    float* adsh = ash + F;
    float* bsh  = adsh + F;

    const int bx = blockIdx.x;
    const int c = bx / NT;
    const int tile = bx % NT;
    const int tid = threadIdx.x;
    const int rowbase = tile * TILE;

    const float* W = Wall + (size_t)c * F * F;
    for (int i = tid; i < F * F / 4; i += 256)
        ((float4*)Ws)[i] = ((const float4*)W)[i];
    if (tid < F) {
        ash[tid]  = asall[c * F + tid];
        adsh[tid] = adall[c * F + tid];
        bsh[tid]  = b1all[c * F + tid];
    }
    __syncthreads();   // bsh read by Xt fill below

    const float* xin = g_x1 + (size_t)c * N_NODES * F;
    float* hout  = g_h2 + (size_t)c * N_NODES * F;
    float* ssout = g_ss2 + (size_t)c * N_NODES;
    float* sdout = g_sd2 + (size_t)c * N_NODES;
    float* wsout = g_ws2 + (size_t)c * N_NODES;

    float* xtf = (float*)Xt;
    #pragma unroll
    for (int it = 0; it < 16; it++) {
        int lin = it * 256 + tid;
        int kg = lin >> 8;
        int row = lin & 255;
        int gr = rowbase + row;
        float4 v = make_float4(0.f, 0.f, 0.f, 0.f);
        if (gr < N_NODES) {
            float4 a = *(const float4*)&xin[(size_t)gr * F + 4 * kg];
            v.x = fmaxf(a.x + bsh[4 * kg + 0], 0.f);
            v.y = fmaxf(a.y + bsh[4 * kg + 1], 0.f);
            v.z = fmaxf(a.z + bsh[4 * kg + 2], 0.f);
            v.w = fmaxf(a.w + bsh[4 * kg + 3], 0.f);
        }
        int base = (4 * kg) * 260 + row;
        xtf[base]       = v.x;
        xtf[base + 260] = v.y;
        xtf[base + 520] = v.z;
        xtf[base + 780] = v.w;
    }
    __syncthreads();

    const int tx = tid & 7;
    const int ty = tid >> 3;
    const ull* xbase = Xt + 4 * ty;
    const float* wbase = Ws + 8 * tx;

    ull acc[4][8];
    #pragma unroll
    for (int i = 0; i < 4; i++)
        #pragma unroll
        for (int j = 0; j < 8; j++) acc[i][j] = 0ull;

    #pragma unroll 4
    for (int k = 0; k < F; k++) {
        float4 wa = *(const float4*)(wbase + k * 64);
        float4 wb = *(const float4*)(wbase + k * 64 + 4);
        ulonglong2 x01 = *(const ulonglong2*)(xbase + k * 130);
        ulonglong2 x23 = *(const ulonglong2*)(xbase + k * 130 + 2);
        ull wd[8];
        wd[0] = dup2(wa.x); wd[1] = dup2(wa.y); wd[2] = dup2(wa.z); wd[3] = dup2(wa.w);
        wd[4] = dup2(wb.x); wd[5] = dup2(wb.y); wd[6] = dup2(wb.z); wd[7] = dup2(wb.w);
        ull xs[4] = {x01.x, x01.y, x23.x, x23.y};
        #pragma unroll
        for (int i = 0; i < 4; i++)
            #pragma unroll
            for (int j = 0; j < 8; j++)
                acc[i][j] = fma2(xs[i], wd[j], acc[i][j]);
    }

    float av[8], dv[8];
    #pragma unroll
    for (int j = 0; j < 8; j++) { av[j] = ash[8 * tx + j]; dv[j] = adsh[8 * tx + j]; }

    float ps[8], pd[8];
    #pragma unroll
    for (int p = 0; p < 4; p++) {
        float lo[8], hi[8];
        #pragma unroll
        for (int j = 0; j < 8; j++) unpack2(acc[p][j], lo[j], hi[j]);
        float s0 = 0.f, d0 = 0.f, s1 = 0.f, d1 = 0.f;
        #pragma unroll
        for (int j = 0; j < 8; j++) {
            s0 += lo[j] * av[j]; d0 += lo[j] * dv[j];
            s1 += hi[j] * av[j]; d1 += hi[j] * dv[j];
        }
        ps[2 * p] = s0; pd[2 * p] = d0; ps[2 * p + 1] = s1; pd[2 * p + 1] = d1;
    }
    #pragma unroll
    for (int off = 1; off < 8; off <<= 1) {
        #pragma unroll
        for (int r = 0; r < 8; r++) {
            ps[r] += __shfl_xor_sync(0xffffffffu, ps[r], off);
            pd[r] += __shfl_xor_sync(0xffffffffu, pd[r], off);
        }
    }

    #pragma unroll
    for (int p = 0; p < 4; p++) {
        int r0 = rowbase + 8 * ty + 2 * p;
        int r1 = r0 + 1;
        float lo[8], hi[8];
        #pragma unroll
        for (int j = 0; j < 8; j++) unpack2(acc[p][j], lo[j], hi[j]);

        if (r0 < N_NODES) {
            *(float4*)&hout[(size_t)r0 * F + 8 * tx]     = make_float4(lo[0], lo[1], lo[2], lo[3]);
            *(float4*)&hout[(size_t)r0 * F + 8 * tx + 4] = make_float4(lo[4], lo[5], lo[6], lo[7]);
            if (tx == 0) {
                float e = ps[2 * p] + pd[2 * p]; e = e > 0.f ? e : NEG * e;
                ssout[r0] = ps[2 * p]; sdout[r0] = pd[2 * p]; wsout[r0] = __expf(e);
            }
        }
        if (r1 < N_NODES) {
            *(float4*)&hout[(size_t)r1 * F + 8 * tx]     = make_float4(hi[0], hi[1], hi[2], hi[3]);
            *(float4*)&hout[(size_t)r1 * F + 8 * tx + 4] = make_float4(hi[4], hi[5], hi[6], hi[7]);
            if (tx == 0) {
                float e = ps[2 * p + 1] + pd[2 * p + 1]; e = e > 0.f ? e : NEG * e;
                ssout[r1] = ps[2 * p + 1]; sdout[r1] = pd[2 * p + 1]; wsout[r1] = __expf(e);
            }
        }
    }
}

// ---------------- CSR build ----------------
__global__ __launch_bounds__(256) void k_zero()
{
    int i = blockIdx.x * 256 + threadIdx.x;
    if (i < M_GROUPS) g_cnt[i] = 0;
}

__global__ __launch_bounds__(256) void k_count(const int* __restrict__ EI, int layer)
{
    int t = blockIdx.x * 256 + threadIdx.x;
    if (t >= M_EDGES) return;
    int c = t / N_EDGES;
    int e = t - c * N_EDGES;
    int d = EI[((size_t)(c * 2 + layer) * 2 + 1) * N_EDGES + e];
    atomicAdd(&g_cnt[c * N_NODES + d], 1);
}

__global__ __launch_bounds__(256) void k_scan1()
{
    __shared__ int sh[256];
    int tid = threadIdx.x;
    int base = blockIdx.x * 1024 + tid * 4;
    int v0 = 0, v1 = 0, v2 = 0, v3 = 0;
    if (base + 3 < M_GROUPS) {
        int4 t = *(const int4*)&g_cnt[base];
        v0 = t.x; v1 = t.y; v2 = t.z; v3 = t.w;
    } else {
        if (base     < M_GROUPS) v0 = g_cnt[base];
        if (base + 1 < M_GROUPS) v1 = g_cnt[base + 1];
        if (base + 2 < M_GROUPS) v2 = g_cnt[base + 2];
        if (base + 3 < M_GROUPS) v3 = g_cnt[base + 3];
    }
    int tsum = v0 + v1 + v2 + v3;
    sh[tid] = tsum;
    __syncthreads();
    for (int off = 1; off < 256; off <<= 1) {
        int t = (tid >= off) ? sh[tid - off] : 0;
        __syncthreads();
        sh[tid] += t;
        __syncthreads();
    }
    int excl = sh[tid] - tsum;
    if (base     < M_GROUPS) g_off[base]     = excl;
    if (base + 1 < M_GROUPS) g_off[base + 1] = excl + v0;
    if (base + 2 < M_GROUPS) g_off[base + 2] = excl + v0 + v1;
    if (base + 3 < M_GROUPS) g_off[base + 3] = excl + v0 + v1 + v2;
    if (tid == 255) g_bsum[blockIdx.x] = sh[255];
}

__global__ __launch_bounds__(1024) void k_scan2()
{
    __shared__ int sh[1024];
    int tid = threadIdx.x;
    int v = (tid < NB_SCAN) ? g_bsum[tid] : 0;
    sh[tid] = v;
    __syncthreads();
    for (int off = 1; off < 1024; off <<= 1) {
        int t = (tid >= off) ? sh[tid - off] : 0;
        __syncthreads();
        sh[tid] += t;
        __syncthreads();
    }
    if (tid < NB_SCAN) g_boff[tid] = sh[tid] - v;
}

__global__ __launch_bounds__(256) void k_scan3()
{
    int i = blockIdx.x * 256 + threadIdx.x;
    if (i >= M_GROUPS) return;
    int v = g_off[i] + g_boff[i >> 10];
    g_off[i] = v;
    g_cur[i] = v;
}

// scatter + per-edge weight; packed (w, src) single 8B store
__global__ __launch_bounds__(256) void k_scatter(const int* __restrict__ EI, int layer)
{
    int t = blockIdx.x * 256 + threadIdx.x;
    if (t >= M_EDGES) return;
    int c = t / N_EDGES;
    int e = t - c * N_EDGES;
    const int* src = EI + ((size_t)(c * 2 + layer) * 2) * N_EDGES;
    const int* dst = src + N_EDGES;
    int s = src[e];
    int d = dst[e];
    const float* ss = (layer ? g_ss2 : g_ss1) + (size_t)c * N_NODES;
    const float* sd = (layer ? g_sd2 : g_sd1) + (size_t)c * N_NODES;
    float ev = __ldg(&ss[s]) + __ldg(&sd[d]);
    ev = ev > 0.f ? ev : NEG * ev;
    float w = __expf(ev);
    int pos = atomicAdd(&g_cur[c * N_NODES + d], 1);
    g_edge[pos] = ((ull)__float_as_uint(w) << 32) | (uint)s;
}

// ---------------- gather aggregation -> normalized x -----------------------
__global__ __launch_bounds__(256) void gat_aggregate(int layer)
{
    int gid = blockIdx.x * 256 + threadIdx.x;
    int g = gid >> 4;
    int j = gid & 15;
    if (g >= M_GROUPS) return;
    int c = g / N_NODES;
    int node = g - c * N_NODES;

    const float* h = (layer ? g_h2 : g_h1) + (size_t)c * N_NODES * F;
    float wself = (layer ? g_ws2 : g_ws1)[g];
    float* xout = (layer ? g_x2 : g_x1) + (size_t)c * N_NODES * F;

    float4 hv = *(const float4*)&h[(size_t)node * F + 4 * j];
    float4 acc = make_float4(wself * hv.x, wself * hv.y, wself * hv.z, wself * hv.w);
    float den = wself;

    int start = g_off[g];
    int end = (g == M_GROUPS - 1) ? M_EDGES : g_off[g + 1];
    for (int i = start; i < end; i++) {
        ull p = __ldg(&g_edge[i]);
        int s = (int)(uint)p;
        float w = __uint_as_float((uint)(p >> 32));
        float4 v = *(const float4*)&h[(size_t)s * F + 4 * j];
        acc.x += w * v.x; acc.y += w * v.y; acc.z += w * v.z; acc.w += w * v.w;
        den += w;
    }
    float inv = 1.f / den;
    *(float4*)&xout[(size_t)node * F + 4 * j] =
        make_float4(acc.x * inv, acc.y * inv, acc.z * inv, acc.w * inv);
}

// ---------------- channel attention combine (x2 already normalized) --------
__global__ __launch_bounds__(256) void gat_final(
    const float* __restrict__ b2, const float* __restrict__ att, float* __restrict__ out)
{
    __shared__ float attsh[NCH * F];
    __shared__ float b2sh[NCH * F];
    for (int i = threadIdx.x; i < NCH * F; i += 256) { attsh[i] = att[i]; b2sh[i] = b2[i]; }
    __syncthreads();

    int tid = blockIdx.x * 256 + threadIdx.x;
    int node = tid >> 4;
    int j = tid & 15;
    if (node >= N_NODES) return;

    float4 xs[NCH];
    float sc[NCH];
    #pragma unroll
    for (int c = 0; c < NCH; c++) {
        float4 v = *(const float4*)&g_x2[((size_t)c * N_NODES + node) * F + 4 * j];
        int cb = c * F + 4 * j;
        v.x += b2sh[cb + 0];
        v.y += b2sh[cb + 1];
        v.z += b2sh[cb + 2];
        v.w += b2sh[cb + 3];
        xs[c] = v;
        sc[c] = v.x * attsh[cb + 0] + v.y * attsh[cb + 1] + v.z * attsh[cb + 2] + v.w * attsh[cb + 3];
    }
    #pragma unroll
    for (int off = 1; off < 16; off <<= 1) {
        #pragma unroll
        for (int c = 0; c < NCH; c++) sc[c] += __shfl_xor_sync(0xffffffffu, sc[c], off);
    }
    float mx = sc[0];
    #pragma unroll
    for (int c = 1; c < NCH; c++) mx = fmaxf(mx, sc[c]);
    float sum = 0.f;
    float wch[NCH];
    #pragma unroll
    for (int c = 0; c < NCH; c++) { wch[c] = __expf(sc[c] - mx); sum += wch[c]; }
    float inv = 1.f / sum;
    float4 o = make_float4(0.f, 0.f, 0.f, 0.f);
    #pragma unroll
    for (int c = 0; c < NCH; c++) {
        float a = wch[c] * inv;
        o.x += a * xs[c].x; o.y += a * xs[c].y; o.z += a * xs[c].z; o.w += a * xs[c].w;
    }
    *(float4*)&out[(size_t)node * F + 4 * j] = o;
}

// ---------------- launch ----------------
extern "C" void kernel_launch(void* const* d_in, const int* in_sizes, int n_in,
                              void* d_out, int out_size)
{
    const float* emb = (const float*)d_in[0];
    const float* W1  = (const float*)d_in[1];
    const float* as1 = (const float*)d_in[2];
    const float* ad1 = (const float*)d_in[3];
    const float* b1  = (const float*)d_in[4];
    const float* W2  = (const float*)d_in[5];
    const float* as2 = (const float*)d_in[6];
    const float* ad2 = (const float*)d_in[7];
    const float* b2  = (const float*)d_in[8];
    const float* att = (const float*)d_in[9];
    const int*   EI  = (const int*)d_in[10];
    float* out = (float*)d_out;

    const int smem_l0 = 16384 + 64 * 130 * 8;               // 82944
    const int smem_l1 = 16384 + 64 * 130 * 8 + 3 * F * 4;   // 83712
    cudaFuncSetAttribute(gat_gemm_l0, cudaFuncAttributeMaxDynamicSharedMemorySize, smem_l0);
    cudaFuncSetAttribute(gat_gemm_l1, cudaFuncAttributeMaxDynamicSharedMemorySize, smem_l1);

    const int grp_grid   = (M_GROUPS + 255) / 256;
    const int edge_grid  = (M_EDGES + 255) / 256;
    const int agg_grid   = (M_GROUPS * 16 + 255) / 256;
    const int fin_grid   = (N_NODES * 16 + 255) / 256;

    // layer 0 — gemm_l0 is the 4th launch (profiled)
    k_zero<<<grp_grid, 256>>>();
    k_count<<<edge_grid, 256>>>(EI, 0);
    k_scan1<<<NB_SCAN, 256>>>();
    gat_gemm_l0<<<NT, 256, smem_l0>>>(emb, W1, as1, ad1);
    k_scan2<<<1, 1024>>>();
    k_scan3<<<grp_grid, 256>>>();
    k_scatter<<<edge_grid, 256>>>(EI, 0);
    gat_aggregate<<<agg_grid, 256>>>(0);

    // layer 1
    k_zero<<<grp_grid, 256>>>();
    k_count<<<edge_grid, 256>>>(EI, 1);
    k_scan1<<<NB_SCAN, 256>>>();
    gat_gemm_l1<<<NCH * NT, 256, smem_l1>>>(W2, as2, ad2, b1);
    k_scan2<<<1, 1024>>>();
    k_scan3<<<grp_grid, 256>>>();
    k_scatter<<<edge_grid, 256>>>(EI, 1);
    gat_aggregate<<<agg_grid, 256>>>(1);

    gat_final<<<fin_grid, 256>>>(b2, att, out);
}